// round 2
// baseline (speedup 1.0000x reference)
#include <cuda_runtime.h>

// ---------------- problem constants ----------------
#define NCL      16        // clusters
#define CSZ      8         // CTAs per cluster
#define NBLK     (NCL*CSZ) // 128 CTAs
#define NTHR     256       // threads per CTA
#define BPC      16        // batch elements per cluster (16*16 = 256)
#define HD       256       // hidden dim
#define DIM      3         // input dim
#define LT       20        // time points
#define NCLASS   10
#define NSTEPS   380       // round((L-1)/0.05)
#define ROWS     32        // output rows owned per CTA
#define WST      260       // weight row stride (floats), K padded 259->260
#define AST      266       // activation per-batch stride (floats) = 133 float2 (bank-safe)
#define K2_IN    130       // float2 pairs for layer 1 (K=259 -> 260)
#define K2_H     128       // float2 pairs for hidden layers (K=256)

// ---------------- smem layout (float offsets) ----------------
#define OFF_W    0                       // [5][ROWS][WST]
#define OFF_B    (5*ROWS*WST)            // [5][ROWS]
#define OFF_T    (OFF_B + 5*ROWS)        // [LT]
#define OFF_Z    (OFF_T + LT)            // [BPC][AST]  z + xt slots (k=256..259)
#define OFF_HB   (OFF_Z + BPC*AST)       // [BPC][AST]  hidden activations
#define SMEM_FLOATS (OFF_HB + BPC*AST)
#define SMEM_BYTES  (SMEM_FLOATS*4)      // ~201 KB

// global scratch for cross-CTA activation exchange (static device mem: allowed)
__device__ float g_h[2][NCL][HD][BPC];
__device__ float g_z[NCL][HD][BPC];

// ---------------- helpers ----------------
__device__ __forceinline__ float2 ffma2(float2 a, float2 b, float2 c) {
    float2 d;
    asm("fma.rn.f32x2 %0, %1, %2, %3;"
        : "=l"(*(unsigned long long*)&d)
        : "l"(*(unsigned long long*)&a),
          "l"(*(unsigned long long*)&b),
          "l"(*(unsigned long long*)&c));
    return d;
}

__device__ __forceinline__ float lipswish(float x) {
    return 0.909f * x / (1.0f + __expf(-x));
}

__device__ __forceinline__ void cluster_bar() {
    asm volatile("barrier.cluster.arrive.aligned;" ::: "memory");
    asm volatile("barrier.cluster.wait.aligned;"   ::: "memory");
}

// dot of one weight row against 2 batch columns, f32x2-packed over K
template<int K2>
__device__ __forceinline__ float2 dotrow(const float* __restrict__ act,
                                         const float* __restrict__ wrow, int bp) {
    const float2* w2 = (const float2*)wrow;
    const float2* i0 = (const float2*)(act + (2*bp  )*AST);
    const float2* i1 = (const float2*)(act + (2*bp+1)*AST);
    float2 a0 = make_float2(0.f, 0.f), a1 = make_float2(0.f, 0.f);
#pragma unroll 16
    for (int kk = 0; kk < K2; kk++) {
        float2 w = w2[kk];
        a0 = ffma2(w, i0[kk], a0);
        a1 = ffma2(w, i1[kk], a1);
    }
    return make_float2(a0.x + a0.y, a1.x + a1.y);
}

// store my 2 outputs for row R to global, cluster-barrier, reload full tile to smem
__device__ __forceinline__ void exchange(float* __restrict__ gb, float2 v, int R, int bp,
                                         float* __restrict__ dst, int tid) {
    *(float2*)(gb + R*BPC + 2*bp) = v;               // STG.64, release via barrier
    cluster_bar();                                    // arrive = release, wait = acquire
    const float2* g2 = (const float2*)gb;
#pragma unroll
    for (int i = 0; i < (HD*BPC/2)/NTHR; i++) {       // 8 iters
        int idx = i*NTHR + tid;
        float2 tv = __ldcg(g2 + idx);                 // L2 (bypass L1: no staleness)
        int k = idx >> 3, p = idx & 7;
        dst[(2*p  )*AST + k] = tv.x;
        dst[(2*p+1)*AST + k] = tv.y;
    }
    __syncthreads();
}

// compute xt (linear interp of control path) into the z-buffer xt slots
__device__ __forceinline__ void write_xt(float* __restrict__ sm,
                                         const float* __restrict__ coeffs,
                                         int cl, int tid, float t) {
    if (tid < BPC) {
        int idx = 0;
#pragma unroll
        for (int i = 1; i <= LT-2; i++) if (sm[OFF_T + i] <= t) idx = i;
        float ta = sm[OFF_T + idx], tb = sm[OFF_T + idx + 1];
        float w = (t - ta) / (tb - ta);
        float omw = 1.0f - w;
        int b = cl*BPC + tid;
        const float* c0 = coeffs + (b*LT + idx)*DIM;
        const float* c1 = c0 + DIM;
        float* zrow = sm + OFF_Z + tid*AST;
        zrow[256] = c0[0]*omw + c1[0]*w;
        zrow[257] = c0[1]*omw + c1[1]*w;
        zrow[258] = c0[2]*omw + c1[2]*w;
        zrow[259] = 0.0f;
    }
}

// ---------------- kernel ----------------
__global__ void __launch_bounds__(NTHR, 1)
ncde_kernel(const float* __restrict__ coeffs, const float* __restrict__ times_g,
            const float* __restrict__ W_init, const float* __restrict__ b_init,
            const float* __restrict__ W_in,   const float* __restrict__ b_in,
            const float* __restrict__ W_hh,   const float* __restrict__ b_hh,
            const float* __restrict__ W_out,  const float* __restrict__ b_out,
            const float* __restrict__ Wc1,    const float* __restrict__ bc1,
            const float* __restrict__ Wc2,    const float* __restrict__ bc2,
            float* __restrict__ out) {
    extern __shared__ float sm[];
    const int tid = threadIdx.x;
    const int cl  = blockIdx.x / CSZ;
    unsigned rank;
    asm("mov.u32 %0, %%cluster_ctarank;" : "=r"(rank));
    const int rowbase = rank * ROWS;
    const int r  = tid >> 3;        // 0..31 local row
    const int bp = tid & 7;         // 0..7 batch pair
    const int R  = rowbase + r;     // global row

    // ---- preload weight slices + biases + times ----
    {
        const float* srcs[5] = {W_in, W_hh, W_hh + HD*HD, W_out, Wc1};
        const int    kw[5]   = {HD + DIM, HD, HD, HD, HD};
        for (int m = 0; m < 5; m++) {
            const float* s = srcs[m];
            const int K = kw[m];
            float* wd = sm + OFF_W + m*ROWS*WST;
            for (int idx = tid; idx < ROWS*WST; idx += NTHR) {
                int rr = idx / WST, k = idx % WST;
                wd[idx] = (k < K) ? s[(rowbase + rr)*K + k] : 0.0f;
            }
        }
        const float* bs[5] = {b_in, b_hh, b_hh + HD, b_out, bc1};
        if (tid < ROWS)
            for (int m = 0; m < 5; m++)
                sm[OFF_B + m*ROWS + tid] = bs[m][rowbase + tid];
        if (tid < LT) sm[OFF_T + tid] = times_g[tid];
    }
    __syncthreads();

    const float t0 = sm[OFF_T];
    const float dt = (sm[OFF_T + LT - 1] - t0) / (float)NSTEPS;
    float t = t0;

    // ---- initial state: xt(t0), then z0 = W_init @ x0 + b_init (all CTAs redundant) ----
    write_xt(sm, coeffs, cl, tid, t);
    __syncthreads();
    for (int idx = tid; idx < HD*BPC; idx += NTHR) {
        int row = idx >> 4, b = idx & 15;
        const float* zr = sm + OFF_Z + b*AST;
        float v = b_init[row]
                + W_init[row*DIM+0]*zr[256]
                + W_init[row*DIM+1]*zr[257]
                + W_init[row*DIM+2]*zr[258];
        sm[OFF_Z + b*AST + row] = v;
    }
    __syncthreads();

    float* gh0 = &g_h[0][cl][0][0];
    float* gh1 = &g_h[1][cl][0][0];
    float* gz  = &g_z[cl][0][0];

    // ---- main Euler loop ----
    for (int s = 0; s < NSTEPS; s++) {
        write_xt(sm, coeffs, cl, tid, t);
        __syncthreads();

        // L1: lipswish(W_in @ [z; x] + b_in)
        float2 v = dotrow<K2_IN>(sm + OFF_Z, sm + OFF_W + 0*ROWS*WST + r*WST, bp);
        float bb = sm[OFF_B + 0*ROWS + r];
        v.x = lipswish(v.x + bb); v.y = lipswish(v.y + bb);
        exchange(gh0, v, R, bp, sm + OFF_HB, tid);

        // L2: lipswish(W_h0 @ h + b_h0)
        v = dotrow<K2_H>(sm + OFF_HB, sm + OFF_W + 1*ROWS*WST + r*WST, bp);
        bb = sm[OFF_B + 1*ROWS + r];
        v.x = lipswish(v.x + bb); v.y = lipswish(v.y + bb);
        exchange(gh1, v, R, bp, sm + OFF_HB, tid);

        // L3: lipswish(W_h1 @ h + b_h1)
        v = dotrow<K2_H>(sm + OFF_HB, sm + OFF_W + 2*ROWS*WST + r*WST, bp);
        bb = sm[OFF_B + 2*ROWS + r];
        v.x = lipswish(v.x + bb); v.y = lipswish(v.y + bb);
        exchange(gh0, v, R, bp, sm + OFF_HB, tid);

        // L4: f = tanh(W_out @ h + b_out); z += dt * f
        v = dotrow<K2_H>(sm + OFF_HB, sm + OFF_W + 3*ROWS*WST + r*WST, bp);
        bb = sm[OFF_B + 3*ROWS + r];
        float f0 = tanhf(v.x + bb), f1 = tanhf(v.y + bb);
        float z0 = sm[OFF_Z + (2*bp  )*AST + R];
        float z1 = sm[OFF_Z + (2*bp+1)*AST + R];
        v.x = fmaf(dt, f0, z0); v.y = fmaf(dt, f1, z1);
        exchange(gz, v, R, bp, sm + OFF_Z, tid);

        t = t + dt;
    }

    // ---- classifier: h = relu(z @ Wc1.T + bc1); out = h @ Wc2.T + bc2 ----
    {
        float2 v = dotrow<K2_H>(sm + OFF_Z, sm + OFF_W + 4*ROWS*WST + r*WST, bp);
        float bb = sm[OFF_B + 4*ROWS + r];
        v.x = fmaxf(v.x + bb, 0.0f); v.y = fmaxf(v.y + bb, 0.0f);
        exchange(gh0, v, R, bp, sm + OFF_HB, tid);

        if (rank == 0 && tid < BPC*NCLASS) {
            int b = tid / NCLASS, c = tid % NCLASS;
            const float* hr = sm + OFF_HB + b*AST;
            const float* wr = Wc2 + c*HD;
            float acc = bc2[c];
#pragma unroll 8
            for (int k = 0; k < HD; k++) acc = fmaf(hr[k], wr[k], acc);
            out[(cl*BPC + b)*NCLASS + c] = acc;
        }
    }
}

// ---------------- launch ----------------
extern "C" void kernel_launch(void* const* d_in, const int* in_sizes, int n_in,
                              void* d_out, int out_size) {
    (void)in_sizes; (void)n_in; (void)out_size;
    cudaFuncSetAttribute(ncde_kernel, cudaFuncAttributeMaxDynamicSharedMemorySize, SMEM_BYTES);

    cudaLaunchConfig_t cfg = {};
    cfg.gridDim  = dim3(NBLK, 1, 1);
    cfg.blockDim = dim3(NTHR, 1, 1);
    cfg.dynamicSmemBytes = SMEM_BYTES;
    cfg.stream = 0;

    cudaLaunchAttribute attrs[1];
    attrs[0].id = cudaLaunchAttributeClusterDimension;
    attrs[0].val.clusterDim.x = CSZ;
    attrs[0].val.clusterDim.y = 1;
    attrs[0].val.clusterDim.z = 1;
    cfg.attrs = attrs;
    cfg.numAttrs = 1;

    cudaLaunchKernelEx(&cfg, ncde_kernel,
        (const float*)d_in[0],  (const float*)d_in[1],
        (const float*)d_in[2],  (const float*)d_in[3],
        (const float*)d_in[4],  (const float*)d_in[5],
        (const float*)d_in[6],  (const float*)d_in[7],
        (const float*)d_in[8],  (const float*)d_in[9],
        (const float*)d_in[10], (const float*)d_in[11],
        (const float*)d_in[12], (const float*)d_in[13],
        (float*)d_out);
}

// round 3
// speedup vs baseline: 1.1424x; 1.1424x over previous
#include <cuda_runtime.h>
#include <cstdint>

#define NCL     16
#define CSZ     8
#define NBLK    (NCL*CSZ)
#define NTHR    256
#define HD      256
#define DIM     3
#define LT      20
#define NCLASS  10
#define NSTEPS  380
#define ROWS    32
#define WST     260     // weight row stride (floats), mult of 4
#define BPC     16

// ---- smem layout (float-word offsets) ----
#define OFF_W   0                     // [5][ROWS][WST] = 41600
#define OFF_B   (5*ROWS*WST)          // [5][ROWS]
#define OFF_T   (OFF_B + 5*ROWS)      // [LT]
#define OFF_MB  (OFF_T + 32)          // 41792 : 8 mbarriers (u64), byte off mult of 8
#define NMB     8
#define OFF_Z   (OFF_MB + NMB*2)      // [65 k4-blocks][16 cols][4]  (block 64 = xt)
#define OFF_H0  (OFF_Z + 65*64)       // [64][16][4]
#define OFF_H1  (OFF_H0 + 64*64)      // [64][16][4]
#define SMEM_WORDS (OFF_H1 + 64*64)
#define SMEM_BYTES (SMEM_WORDS*4)     // ~216.6 KB

// activation element word-offset inside a buffer: k, col
#define AOFF(k,c) (((k)>>2)*64 + (c)*4 + ((k)&3))

// mbarrier logical index: layer l in {0:h0,1:h1,2:h2(alias h0),3:z}, group g
#define MBI(l,g) ((l)*2+(g))
#define TXB 8192u   // bytes per barrier per phase: 256 rows * 8 cols * 4B

// ---------------- helpers ----------------
__device__ __forceinline__ float2 ffma2(float2 a, float2 b, float2 c) {
    float2 d;
    asm("fma.rn.f32x2 %0, %1, %2, %3;"
        : "=l"(*(unsigned long long*)&d)
        : "l"(*(unsigned long long*)&a),
          "l"(*(unsigned long long*)&b),
          "l"(*(unsigned long long*)&c));
    return d;
}
__device__ __forceinline__ float lipswish(float x) {
    return 0.909f * x / (1.0f + __expf(-x));
}
__device__ __forceinline__ uint32_t smem_u32(const void* p) {
    uint32_t a;
    asm("{ .reg .u64 t; cvta.to.shared.u64 t, %1; cvt.u32.u64 %0, t; }" : "=r"(a) : "l"(p));
    return a;
}
__device__ __forceinline__ uint32_t mapa_u32(uint32_t a, uint32_t rank) {
    uint32_t d;
    asm("mapa.shared::cluster.u32 %0, %1, %2;" : "=r"(d) : "r"(a), "r"(rank));
    return d;
}
__device__ __forceinline__ void cluster_bar() {
    asm volatile("barrier.cluster.arrive.aligned;" ::: "memory");
    asm volatile("barrier.cluster.wait.aligned;"   ::: "memory");
}
__device__ __forceinline__ void mb_init(uint32_t mb, uint32_t cnt) {
    asm volatile("mbarrier.init.shared.b64 [%0], %1;" :: "r"(mb), "r"(cnt) : "memory");
}
__device__ __forceinline__ void mb_arm(uint32_t mb, uint32_t tx) {
    asm volatile("mbarrier.arrive.expect_tx.shared.b64 _, [%0], %1;" :: "r"(mb), "r"(tx) : "memory");
}
__device__ __forceinline__ void mb_wait(uint32_t mb, uint32_t parity) {
    uint32_t done;
    asm volatile(
        "{\n\t.reg .pred p;\n\t"
        "mbarrier.try_wait.parity.acquire.cta.shared::cta.b64 p, [%1], %2, 0x989680;\n\t"
        "selp.b32 %0, 1, 0, p;\n\t}"
        : "=r"(done) : "r"(mb), "r"(parity) : "memory");
    while (!done) {
        asm volatile(
            "{\n\t.reg .pred p;\n\t"
            "mbarrier.try_wait.parity.acquire.cta.shared::cta.b64 p, [%1], %2, 0x989680;\n\t"
            "selp.b32 %0, 1, 0, p;\n\t}"
            : "=r"(done) : "r"(mb), "r"(parity) : "memory");
    }
}
// scatter one value to (R,c) of buffer bufw in ALL 8 CTAs, completing their mbarrier
__device__ __forceinline__ void scatter(const uint32_t* __restrict__ pb,
                                        int bufw, int mbi, int R, int c, float v) {
    uint32_t eoff = (uint32_t)(bufw + AOFF(R, c)) * 4u;
    uint32_t moff = (uint32_t)(OFF_MB * 4 + mbi * 8);
#pragma unroll
    for (int rr = 0; rr < CSZ; rr++) {
        asm volatile(
            "st.async.weak.shared::cluster.mbarrier::complete_tx::bytes.b32 [%0], %1, [%2];"
            :: "r"(pb[rr] + eoff), "f"(v), "r"(pb[rr] + moff) : "memory");
    }
}

// dot of weight row (float4, contiguous) vs activation column (float4, stride 16)
template<int NK4>
__device__ __forceinline__ float dotf(const float4* __restrict__ w, const float4* __restrict__ a) {
    float2 s0 = make_float2(0.f, 0.f), s1 = make_float2(0.f, 0.f);
#pragma unroll 16
    for (int k = 0; k < NK4; k++) {
        float4 wv = w[k];
        float4 av = a[k * 16];
        s0 = ffma2(make_float2(wv.x, wv.y), make_float2(av.x, av.y), s0);
        s1 = ffma2(make_float2(wv.z, wv.w), make_float2(av.z, av.w), s1);
    }
    return (s0.x + s0.y) + (s1.x + s1.y);
}

// ---------------- kernel ----------------
__global__ void __launch_bounds__(NTHR, 1)
ncde_kernel(const float* __restrict__ coeffs, const float* __restrict__ times_g,
            const float* __restrict__ W_init, const float* __restrict__ b_init,
            const float* __restrict__ W_in,   const float* __restrict__ b_in,
            const float* __restrict__ W_hh,   const float* __restrict__ b_hh,
            const float* __restrict__ W_out,  const float* __restrict__ b_out,
            const float* __restrict__ Wc1,    const float* __restrict__ bc1,
            const float* __restrict__ Wc2,    const float* __restrict__ bc2,
            float* __restrict__ out) {
    extern __shared__ float sm[];
    const int tid = threadIdx.x;
    const int cl  = blockIdx.x / CSZ;
    unsigned rank;
    asm("mov.u32 %0, %%cluster_ctarank;" : "=r"(rank));
    const int r  = tid >> 3;          // 0..31 local row
    const int c  = tid & 7;           // 0..7 col within group
    const int R  = rank * ROWS + r;   // global row 0..255

    const uint32_t smb = smem_u32(sm);
    uint32_t pb[CSZ];
#pragma unroll
    for (int rr = 0; rr < CSZ; rr++) pb[rr] = mapa_u32(smb, rr);
#define MBA(i) (smb + OFF_MB*4 + (i)*8)

    // ---- preload weights (zero-padded rows), biases, times ----
    {
        const float* srcs[5] = {W_in, W_hh, W_hh + HD*HD, W_out, Wc1};
        const int    kw[5]   = {HD + DIM, HD, HD, HD, HD};
#pragma unroll
        for (int m = 0; m < 5; m++) {
            const float* s = srcs[m];
            const int K = kw[m];
            float* wd = sm + OFF_W + m*ROWS*WST;
            for (int idx = tid; idx < ROWS*WST; idx += NTHR) {
                int rr2 = idx / WST, k = idx % WST;
                wd[idx] = (k < K) ? s[(rank*ROWS + rr2)*K + k] : 0.0f;
            }
        }
        const float* bs[5] = {b_in, b_hh, b_hh + HD, b_out, bc1};
        if (tid < ROWS)
#pragma unroll
            for (int m = 0; m < 5; m++)
                sm[OFF_B + m*ROWS + tid] = bs[m][rank*ROWS + tid];
        if (tid < LT) sm[OFF_T + tid] = times_g[tid];
    }
    // ---- mbarrier init + arm phase 0 ----
    if (tid == 0) {
#pragma unroll
        for (int i = 0; i < NMB; i++) { mb_init(MBA(i), 1); mb_arm(MBA(i), TXB); }
    }
    __syncthreads();
    cluster_bar();   // all CTAs' barriers live before any st.async

    const float t0 = sm[OFF_T];
    const float dt = (sm[OFF_T + LT - 1] - t0) / (float)NSTEPS;
    float t = t0;

    // ---- xt(t) into z-buffer block 64 (cols 0..15), local only ----
    auto write_xt = [&](float tt) {
        if (tid < BPC) {
            int idx = 0;
#pragma unroll
            for (int i = 1; i <= LT - 2; i++) if (sm[OFF_T + i] <= tt) idx = i;
            float ta = sm[OFF_T + idx], tb = sm[OFF_T + idx + 1];
            float w = (tt - ta) / (tb - ta), omw = 1.0f - w;
            const float* c0 = coeffs + ((cl*BPC + tid)*LT + idx)*DIM;
            const float* c1 = c0 + DIM;
            float4 xv;
            xv.x = c0[0]*omw + c1[0]*w;
            xv.y = c0[1]*omw + c1[1]*w;
            xv.z = c0[2]*omw + c1[2]*w;
            xv.w = 0.0f;
            *(float4*)(sm + OFF_Z + 64*64 + tid*4) = xv;
        }
    };

    // ---- z0 = W_init @ x(t0) + b_init, replicated in every CTA ----
    write_xt(t);
    __syncthreads();
    for (int i = 0; i < (HD*BPC)/NTHR; i++) {
        int idx = i*NTHR + tid;
        int col = idx & 15, row = idx >> 4;
        const float* xv = sm + OFF_Z + 64*64 + col*4;
        float v = b_init[row]
                + W_init[row*DIM+0]*xv[0]
                + W_init[row*DIM+1]*xv[1]
                + W_init[row*DIM+2]*xv[2];
        sm[OFF_Z + AOFF(row, col)] = v;
    }
    __syncthreads();

    const bool lead = (tid == 0);
    const float4* wm0 = (const float4*)(sm + OFF_W + 0*ROWS*WST + r*WST);
    const float4* wm1 = (const float4*)(sm + OFF_W + 1*ROWS*WST + r*WST);
    const float4* wm2 = (const float4*)(sm + OFF_W + 2*ROWS*WST + r*WST);
    const float4* wm3 = (const float4*)(sm + OFF_W + 3*ROWS*WST + r*WST);
    const float4* az  = (const float4*)(sm + OFF_Z);
    const float4* ah0 = (const float4*)(sm + OFF_H0);
    const float4* ah1 = (const float4*)(sm + OFF_H1);
    const float bi0 = sm[OFF_B + 0*ROWS + r];
    const float bi1 = sm[OFF_B + 1*ROWS + r];
    const float bi2 = sm[OFF_B + 2*ROWS + r];
    const float bi3 = sm[OFF_B + 3*ROWS + r];
    const int cA = c, cB = c + 8;

    // ---- main Euler loop: 2-group pipelined, DSMEM all-to-all per layer ----
    for (int s = 0; s < NSTEPS; s++) {
        const uint32_t ph  = (uint32_t)(s & 1);
        const uint32_t pz  = ph ^ 1u;   // z data scattered during step s-1

        write_xt(t);
        __syncthreads();

        // L1 = lipswish(W_in @ [z;x])
        if (s) { mb_wait(MBA(MBI(3,0)), pz); if (lead) mb_arm(MBA(MBI(3,0)), TXB); }
        {
            float v = lipswish(dotf<65>(wm0, az + cA) + bi0);
            scatter(pb, OFF_H0, MBI(0,0), R, cA, v);
        }
        if (s) { mb_wait(MBA(MBI(3,1)), pz); if (lead) mb_arm(MBA(MBI(3,1)), TXB); }
        {
            float v = lipswish(dotf<65>(wm0, az + cB) + bi0);
            scatter(pb, OFF_H0, MBI(0,1), R, cB, v);
        }
        // L2
        mb_wait(MBA(MBI(0,0)), ph); if (lead) mb_arm(MBA(MBI(0,0)), TXB);
        {
            float v = lipswish(dotf<64>(wm1, ah0 + cA) + bi1);
            scatter(pb, OFF_H1, MBI(1,0), R, cA, v);
        }
        mb_wait(MBA(MBI(0,1)), ph); if (lead) mb_arm(MBA(MBI(0,1)), TXB);
        {
            float v = lipswish(dotf<64>(wm1, ah0 + cB) + bi1);
            scatter(pb, OFF_H1, MBI(1,1), R, cB, v);
        }
        // L3 (output overwrites H0; guarded by h1 barrier semantics)
        mb_wait(MBA(MBI(1,0)), ph); if (lead) mb_arm(MBA(MBI(1,0)), TXB);
        {
            float v = lipswish(dotf<64>(wm2, ah1 + cA) + bi2);
            scatter(pb, OFF_H0, MBI(2,0), R, cA, v);
        }
        mb_wait(MBA(MBI(1,1)), ph); if (lead) mb_arm(MBA(MBI(1,1)), TXB);
        {
            float v = lipswish(dotf<64>(wm2, ah1 + cB) + bi2);
            scatter(pb, OFF_H0, MBI(2,1), R, cB, v);
        }
        // L4: z <- z + dt * tanh(W_out @ h)
        mb_wait(MBA(MBI(2,0)), ph); if (lead) mb_arm(MBA(MBI(2,0)), TXB);
        {
            float f = tanhf(dotf<64>(wm3, ah0 + cA) + bi3);
            float zo = sm[OFF_Z + AOFF(R, cA)];
            scatter(pb, OFF_Z, MBI(3,0), R, cA, fmaf(dt, f, zo));
        }
        mb_wait(MBA(MBI(2,1)), ph); if (lead) mb_arm(MBA(MBI(2,1)), TXB);
        {
            float f = tanhf(dotf<64>(wm3, ah0 + cB) + bi3);
            float zo = sm[OFF_Z + AOFF(R, cB)];
            scatter(pb, OFF_Z, MBI(3,1), R, cB, fmaf(dt, f, zo));
        }
        t = t + dt;
    }

    // ---- final z arrivals (scattered at step NSTEPS-1, parity 1) ----
    mb_wait(MBA(MBI(3,0)), 1u);
    mb_wait(MBA(MBI(3,1)), 1u);

    // ---- classifier hidden: relu(Wc1 @ z), scatter into H1 (phase NSTEPS, parity 0) ----
    {
        const float4* wm4 = (const float4*)(sm + OFF_W + 4*ROWS*WST + r*WST);
        const float bi4 = sm[OFF_B + 4*ROWS + r];
        float v = fmaxf(dotf<64>(wm4, az + cA) + bi4, 0.0f);
        scatter(pb, OFF_H1, MBI(1,0), R, cA, v);
        v = fmaxf(dotf<64>(wm4, az + cB) + bi4, 0.0f);
        scatter(pb, OFF_H1, MBI(1,1), R, cB, v);
    }
    mb_wait(MBA(MBI(1,0)), 0u);
    mb_wait(MBA(MBI(1,1)), 0u);

    // ---- stage Wc2/bc2 in smem (reuse H0 area), then rank 0 writes output ----
    for (int i = tid; i < NCLASS*HD; i += NTHR) sm[OFF_H0 + i] = Wc2[i];
    if (tid < NCLASS) sm[OFF_H0 + NCLASS*HD + tid] = bc2[tid];
    __syncthreads();

    if (rank == 0 && tid < BPC*NCLASS) {
        int b = tid & 15, cls = tid >> 4;
        float acc = sm[OFF_H0 + NCLASS*HD + cls];
        const float* wr = sm + OFF_H0 + cls*HD;
#pragma unroll 8
        for (int k = 0; k < HD; k++)
            acc = fmaf(sm[OFF_H1 + AOFF(k, b)], wr[k], acc);
        out[(cl*BPC + b)*NCLASS + cls] = acc;
    }

    cluster_bar();   // no CTA exits while peers may still target its smem
}

// ---------------- launch ----------------
extern "C" void kernel_launch(void* const* d_in, const int* in_sizes, int n_in,
                              void* d_out, int out_size) {
    (void)in_sizes; (void)n_in; (void)out_size;
    cudaFuncSetAttribute(ncde_kernel, cudaFuncAttributeMaxDynamicSharedMemorySize, SMEM_BYTES);

    cudaLaunchConfig_t cfg = {};
    cfg.gridDim  = dim3(NBLK, 1, 1);
    cfg.blockDim = dim3(NTHR, 1, 1);
    cfg.dynamicSmemBytes = SMEM_BYTES;
    cfg.stream = 0;

    cudaLaunchAttribute attrs[1];
    attrs[0].id = cudaLaunchAttributeClusterDimension;
    attrs[0].val.clusterDim.x = CSZ;
    attrs[0].val.clusterDim.y = 1;
    attrs[0].val.clusterDim.z = 1;
    cfg.attrs = attrs;
    cfg.numAttrs = 1;

    cudaLaunchKernelEx(&cfg, ncde_kernel,
        (const float*)d_in[0],  (const float*)d_in[1],
        (const float*)d_in[2],  (const float*)d_in[3],
        (const float*)d_in[4],  (const float*)d_in[5],
        (const float*)d_in[6],  (const float*)d_in[7],
        (const float*)d_in[8],  (const float*)d_in[9],
        (const float*)d_in[10], (const float*)d_in[11],
        (const float*)d_in[12], (const float*)d_in[13],
        (float*)d_out);
}